// round 1
// baseline (speedup 1.0000x reference)
#include <cuda_runtime.h>
#include <math.h>

#define MAX_BLOCKS 4096

__device__ double g_partials[MAX_BLOCKS];

template <int BT>
__global__ void phi_kernel(const float* __restrict__ CA,
                           const float* __restrict__ CB,
                           const float* __restrict__ coeff,
                           const float* __restrict__ cutoffs,
                           const int* __restrict__ xidx,
                           const int* __restrict__ yidx,
                           int P, int Bv, int Lv, int Kc) {
    __shared__ float s_cut[64];
    __shared__ double s_warp[16];

    for (int k = threadIdx.x; k < Kc; k += blockDim.x) s_cut[k] = cutoffs[k];
    __syncthreads();

    const int nInt = Kc - 1;
    float acc = 0.0f;

    for (int p = blockIdx.x * blockDim.x + threadIdx.x; p < P;
         p += gridDim.x * blockDim.x) {
        const int xi = xidx[p];
        const int yi = yidx[p];
        const float4* cf =
            reinterpret_cast<const float4*>(coeff) + (size_t)(xi * Lv + yi) * nInt;

        const int Bn = (BT > 0) ? BT : Bv;
        #pragma unroll
        for (int b = 0; b < Bn; b++) {
            const float* pca  = CA + ((size_t)b * Lv + xi) * 3;
            const float* pcbx = CB + ((size_t)b * Lv + xi) * 3;
            const float* pcby = CB + ((size_t)b * Lv + yi) * 3;

            const float bx0 = pcbx[0], bx1 = pcbx[1], bx2 = pcbx[2];
            const float x0 = pca[0] - bx0, x1 = pca[1] - bx1, x2 = pca[2] - bx2;
            const float y0 = pcby[0] - bx0, y1 = pcby[1] - bx1, y2 = pcby[2] - bx2;

            const float nx2 = x0 * x0 + x1 * x1 + x2 * x2;
            const float ny2 = y0 * y0 + y1 * y1 + y2 * y2;
            const float dt  = x0 * y0 + x1 * y1 + x2 * y2;

            // valid: ||x|| > 1e-6 && ||y|| > 1e-6  (compare squared norms)
            if (nx2 > 1e-12f && ny2 > 1e-12f) {
                const float c = dt / sqrtf(nx2 * ny2);
                // good: 1 - c^2 > 1e-6
                if (1.0f - c * c > 1e-6f) {
                    // clip is a no-op when 'good' holds (|c| < 0.9999995), but
                    // apply it anyway for exact parity with the reference
                    float cc = fminf(fmaxf(c, -0.9999999f), 0.9999999f);
                    const float phi = acosf(cc);

                    // searchsorted(cutoffs, phi, 'left') - 1, clipped to [0, nInt-1]
                    int cnt = 0;
                    #pragma unroll
                    for (int k = 0; k < 16; k++) {
                        if (k < Kc && s_cut[k] < phi) cnt++;
                    }
                    int idx = cnt - 1;
                    idx = idx < 0 ? 0 : (idx > nInt - 1 ? nInt - 1 : idx);

                    const float dx = phi - s_cut[idx];
                    const float4 cs = __ldg(&cf[idx]);
                    // val = c3 + dx*(c2 + dx*(c1 + dx*c0))
                    acc += cs.w + dx * (cs.z + dx * (cs.y + dx * cs.x));
                }
            }
        }
    }

    // deterministic block reduction: warp shuffle (float) -> smem (double)
    #pragma unroll
    for (int off = 16; off > 0; off >>= 1)
        acc += __shfl_down_sync(0xffffffffu, acc, off);

    const int warp = threadIdx.x >> 5;
    if ((threadIdx.x & 31) == 0) s_warp[warp] = (double)acc;
    __syncthreads();

    if (threadIdx.x == 0) {
        double t = 0.0;
        const int nw = (blockDim.x + 31) >> 5;
        for (int w = 0; w < nw; w++) t += s_warp[w];
        g_partials[blockIdx.x] = t;
    }
}

__global__ void reduce_kernel(float* __restrict__ out, int nblk) {
    __shared__ double s[512];
    double v = 0.0;
    for (int i = threadIdx.x; i < nblk; i += blockDim.x) v += g_partials[i];
    s[threadIdx.x] = v;
    __syncthreads();
    for (int off = blockDim.x >> 1; off > 0; off >>= 1) {
        if ((int)threadIdx.x < off) s[threadIdx.x] += s[threadIdx.x + off];
        __syncthreads();
    }
    if (threadIdx.x == 0) out[0] = (float)s[0];
}

extern "C" void kernel_launch(void* const* d_in, const int* in_sizes, int n_in,
                              void* d_out, int out_size) {
    const float* CA      = (const float*)d_in[0];
    const float* CB      = (const float*)d_in[1];
    const float* coeff   = (const float*)d_in[2];
    const float* cutoffs = (const float*)d_in[3];
    const int*   xidx    = (const int*)d_in[4];
    const int*   yidx    = (const int*)d_in[5];

    const int Kc = in_sizes[3];          // number of knots (16)
    const int P  = in_sizes[4];          // number of pairs (80000)
    const long long ce = in_sizes[2];    // L*L*(Kc-1)*4
    const int Lv = (int)(sqrt((double)(ce / ((long long)(Kc - 1) * 4))) + 0.5);
    const int Bv = in_sizes[0] / (Lv * 3);

    const int threads = 256;
    int nblk = (P + threads - 1) / threads;
    if (nblk > MAX_BLOCKS) nblk = MAX_BLOCKS;

    if (Bv == 8) {
        phi_kernel<8><<<nblk, threads>>>(CA, CB, coeff, cutoffs, xidx, yidx,
                                         P, Bv, Lv, Kc);
    } else {
        phi_kernel<0><<<nblk, threads>>>(CA, CB, coeff, cutoffs, xidx, yidx,
                                         P, Bv, Lv, Kc);
    }
    reduce_kernel<<<1, 512>>>((float*)d_out, nblk);
}